// round 1
// baseline (speedup 1.0000x reference)
#include <cuda_runtime.h>

// Correlation layer: out[b, i*41+j, y, x] =
//   (1/576) * sum_c in1[b,c,y,x] * in2[b,c, y-2*(j-10), x-2*(i-10)]
// in1,in2: [4,64,96,160] f32 ; out: [4,1681,96,160] f32
//
// Strategy: dx is always even -> x and x-dx have the same parity -> operate on
// float2 (even,odd) pairs with packed fma.rn.f32x2 (2x fp32 FMA throughput).
// One block per (b, y, j). smem-staged 16-channel chunks. Register-tiled
// stencil: thread tile = 10 float2 (x-pairs) x 6 displacements; k-window of
// 15 contiguous float2 shared across the tile.

#define THREADS 64
#define CK      16          // channels per smem chunk
#define W       160
#define H       96
#define C       64
#define BATCH   4
#define D       41
#define UW      80          // float2 per image row
#define S2W     128         // s2 row width in float2 (covers u2 in [-38, 90))
#define TU      10          // float2 per thread along x
#define TI      6           // displacements per thread
#define NTI     7           // 7 * 6 = 42 >= 41

typedef unsigned long long u64;

__device__ __forceinline__ u64 ffma2(u64 a, u64 b, u64 c) {
    u64 d;
    asm("fma.rn.f32x2 %0, %1, %2, %3;" : "=l"(d) : "l"(a), "l"(b), "l"(c));
    return d;
}

__global__ __launch_bounds__(THREADS, 4)
void corr_kernel(const float* __restrict__ in1,
                 const float* __restrict__ in2,
                 float* __restrict__ out) {
    const int j = blockIdx.x;   // dy index, 0..40
    const int y = blockIdx.y;   // 0..95
    const int b = blockIdx.z;   // 0..3
    const int dy = (j - 10) * 2;
    const int y2 = y - dy;
    const int t  = threadIdx.x;

    // out[((b*1681 + i*41 + j)*96 + y)*160 + x]
    float* outbase = out + ((size_t)(b * (D * D) + j) * H + y) * W;
    const size_t ostride_i = (size_t)D * H * W;   // stride between i-channels

    if (y2 < 0 || y2 >= H) {
        // entire (y, j) slab is zero for all 41 i-channels
        for (int i = 0; i < D; i++) {
            float4* row = (float4*)(outbase + (size_t)i * ostride_i);
            for (int idx = t; idx < W / 4; idx += THREADS)
                row[idx] = make_float4(0.f, 0.f, 0.f, 0.f);
        }
        return;
    }

    __shared__ u64 s1[CK][UW];    // in1 row (float2 pairs)
    __shared__ u64 s2[CK][S2W];   // in2 row, zero padded; su = u2 + 38

    const int tu = t & 7;         // 8 u-tiles of 10 float2 -> 80
    const int ti = t >> 3;        // 0..7 ; ti == 7 inactive
    const bool active = (ti < NTI);

    u64 acc[TI][TU];
#pragma unroll
    for (int a = 0; a < TI; a++)
#pragma unroll
        for (int q = 0; q < TU; q++) acc[a][q] = 0ULL;

    const float* in1base = in1 + ((size_t)(b * C) * H + y)  * W;
    const float* in2base = in2 + ((size_t)(b * C) * H + y2) * W;
    const int crow = H * W;

    // k-window: su(uu,ii) = 10*tu - 6*ti + 48 + uu - ii, uu in [0,10), ii in [0,6)
    // su_min = 10*tu - 6*ti + 43 (always odd) -> abase = su_min - 1 (even, 16B aligned)
    const int abase = 10 * tu - 6 * ti + 42;

    for (int c0 = 0; c0 < C; c0 += CK) {
        __syncthreads();   // previous chunk's compute done before overwrite

        // stage in1 chunk: CK rows x 160 floats (40 float4 each)
        for (int idx = t; idx < CK * (W / 4); idx += THREADS) {
            int cc = idx / (W / 4);
            int xw = idx % (W / 4);
            float4 v = *(const float4*)(in1base + (size_t)(c0 + cc) * crow + xw * 4);
            ((float4*)&s1[cc][0])[xw] = v;
        }
        // stage in2 chunk with zero padding: CK rows x 128 float2
        for (int idx = t; idx < CK * S2W; idx += THREADS) {
            int cc = idx >> 7;
            int su = idx & (S2W - 1);
            int xf = 2 * (su - 38);
            float2 v = make_float2(0.f, 0.f);
            if (xf >= 0 && xf < W)
                v = *(const float2*)(in2base + (size_t)(c0 + cc) * crow + xf);
            *(float2*)&s2[cc][su] = v;
        }
        __syncthreads();

        if (active) {
#pragma unroll 2
            for (int cc = 0; cc < CK; cc++) {
                u64 q[TU];
                {
                    const ulonglong2* p = (const ulonglong2*)&s1[cc][tu * TU];
#pragma unroll
                    for (int h = 0; h < TU / 2; h++) {
                        ulonglong2 v = p[h];
                        q[2 * h] = v.x; q[2 * h + 1] = v.y;
                    }
                }
                u64 k[16];
                {
                    const ulonglong2* p = (const ulonglong2*)&s2[cc][abase];
#pragma unroll
                    for (int h = 0; h < 8; h++) {
                        ulonglong2 v = p[h];
                        k[2 * h] = v.x; k[2 * h + 1] = v.y;
                    }
                }
#pragma unroll
                for (int ii = 0; ii < TI; ii++)
#pragma unroll
                    for (int uu = 0; uu < TU; uu++)
                        acc[ii][uu] = ffma2(q[uu], k[uu - ii + 6], acc[ii][uu]);
            }
        }
    }

    if (active) {
        const float scale = 1.0f / 576.0f;   // 1 / (C * kernel^2) = 1/(64*9)
#pragma unroll
        for (int ii = 0; ii < TI; ii++) {
            int i = ti * TI + ii;
            if (i >= D) continue;            // covers the single padded i=41
            float* row = outbase + (size_t)i * ostride_i + 20 * tu;
#pragma unroll
            for (int uu = 0; uu < TU; uu++) {
                float2 v = *(float2*)&acc[ii][uu];
                v.x *= scale; v.y *= scale;
                *(float2*)(row + 2 * uu) = v;
            }
        }
    }
}

extern "C" void kernel_launch(void* const* d_in, const int* in_sizes, int n_in,
                              void* d_out, int out_size) {
    const float* in1 = (const float*)d_in[0];
    const float* in2 = (const float*)d_in[1];
    dim3 grid(D, H, BATCH);
    corr_kernel<<<grid, THREADS>>>(in1, in2, (float*)d_out);
}

// round 2
// speedup vs baseline: 1.4198x; 1.4198x over previous
#include <cuda_runtime.h>

// Correlation layer: out[b, i*41+j, y, x] =
//   (1/576) * sum_c in1[b,c,y,x] * in2[b,c, y-2*(j-10), x-2*(i-10)]
// in1,in2: [4,64,96,160] f32 ; out: [4,1681,96,160] f32
//
// dx always even -> work on float2 (even,odd) pairs with packed fma.rn.f32x2.
// One block per (b, y, j). cp.async double-buffered 8-channel chunks so
// global->smem staging overlaps compute. Register-tiled stencil:
// 10 float2 x 6 displacements per thread, 15-f2 k-window in registers.

#define THREADS 64
#define CK      8           // channels per smem chunk (double buffered)
#define W       160
#define H       96
#define C       64
#define BATCH   4
#define D       41
#define UW      80          // float2 per image row
#define S2W     128         // s2 row width in float2 (su = u2 + 38)
#define TU      10          // float2 per thread along x
#define TI      6           // displacements per thread
#define NTI     7           // 7 * 6 = 42 >= 41

typedef unsigned long long u64;

__device__ __forceinline__ u64 ffma2(u64 a, u64 b, u64 c) {
    u64 d;
    asm("fma.rn.f32x2 %0, %1, %2, %3;" : "=l"(d) : "l"(a), "l"(b), "l"(c));
    return d;
}

__device__ __forceinline__ void cp16(u64* dst, const float* src) {
    unsigned sa = (unsigned)__cvta_generic_to_shared(dst);
    asm volatile("cp.async.cg.shared.global [%0], [%1], 16;\n"
                 :: "r"(sa), "l"(src));
}
__device__ __forceinline__ void cp_commit() {
    asm volatile("cp.async.commit_group;\n" ::);
}
template <int N>
__device__ __forceinline__ void cp_wait() {
    asm volatile("cp.async.wait_group %0;\n" :: "n"(N));
}

__global__ __launch_bounds__(THREADS, 4)
void corr_kernel(const float* __restrict__ in1,
                 const float* __restrict__ in2,
                 float* __restrict__ out) {
    const int j = blockIdx.x;   // dy index, 0..40
    const int y = blockIdx.y;   // 0..95
    const int b = blockIdx.z;   // 0..3
    const int dy = (j - 10) * 2;
    const int y2 = y - dy;
    const int t  = threadIdx.x;

    float* outbase = out + ((size_t)(b * (D * D) + j) * H + y) * W;
    const size_t ostride_i = (size_t)D * H * W;

    if (y2 < 0 || y2 >= H) {
        for (int i = 0; i < D; i++) {
            float4* row = (float4*)(outbase + (size_t)i * ostride_i);
            for (int idx = t; idx < W / 4; idx += THREADS)
                row[idx] = make_float4(0.f, 0.f, 0.f, 0.f);
        }
        return;
    }

    __shared__ u64 s1[2][CK][UW];    // in1 row chunks (float2 pairs)
    __shared__ u64 s2[2][CK][S2W];   // in2 row chunks, zero padded

    const int tu = t & 7;            // 8 u-tiles of 10 float2 -> 80
    const int ti = t >> 3;           // 0..7 ; ti == 7 inactive in compute
    const bool active = (ti < NTI);

    const float* in1base = in1 + ((size_t)(b * C) * H + y)  * W;
    const float* in2base = in2 + ((size_t)(b * C) * H + y2) * W;
    const int crow = H * W;

    // zero the s2 borders once (su < 38 or su >= 118) — never overwritten
    for (int idx = t; idx < 2 * CK * 48; idx += THREADS) {
        int r = idx / 48;
        int z = idx % 48;
        int su = (z < 38) ? z : (118 + z - 38);
        (&s2[0][0][0])[r * S2W + su] = 0ULL;
    }

    u64 acc[TI][TU];
#pragma unroll
    for (int a = 0; a < TI; a++)
#pragma unroll
        for (int q = 0; q < TU; q++) acc[a][q] = 0ULL;

    // k-window base: su_min = 10*tu - 6*ti + 43 (odd) -> abase even, 16B aligned
    const int abase = 10 * tu - 6 * ti + 42;

    // --- cp.async staging: CK rows x 40 x 16B for each of s1, s2 ---
    auto stage = [&](int buf, int c0) {
        const float* p1 = in1base + (size_t)c0 * crow;
        const float* p2 = in2base + (size_t)c0 * crow;
#pragma unroll
        for (int it = 0; it < (CK * 40) / THREADS; it++) {
            int idx = it * THREADS + t;
            int cc = idx / 40;
            int m  = idx % 40;
            cp16(&s1[buf][cc][m * 2],        p1 + (size_t)cc * crow + m * 4);
            cp16(&s2[buf][cc][38 + m * 2],   p2 + (size_t)cc * crow + m * 4);
        }
    };

    const int NCHUNK = C / CK;   // 8
    stage(0, 0);
    cp_commit();

    for (int n = 0; n < NCHUNK; n++) {
        if (n + 1 < NCHUNK) {
            stage((n + 1) & 1, (n + 1) * CK);
            cp_commit();
            cp_wait<1>();
        } else {
            cp_wait<0>();
        }
        __syncthreads();

        const int buf = n & 1;
        if (active) {
#pragma unroll 2
            for (int cc = 0; cc < CK; cc++) {
                u64 q[TU];
                {
                    const ulonglong2* p = (const ulonglong2*)&s1[buf][cc][tu * TU];
#pragma unroll
                    for (int h = 0; h < TU / 2; h++) {
                        ulonglong2 v = p[h];
                        q[2 * h] = v.x; q[2 * h + 1] = v.y;
                    }
                }
                u64 k[16];
                {
                    const ulonglong2* p = (const ulonglong2*)&s2[buf][cc][abase];
#pragma unroll
                    for (int h = 0; h < 8; h++) {
                        ulonglong2 v = p[h];
                        k[2 * h] = v.x; k[2 * h + 1] = v.y;
                    }
                }
#pragma unroll
                for (int ii = 0; ii < TI; ii++)
#pragma unroll
                    for (int uu = 0; uu < TU; uu++)
                        acc[ii][uu] = ffma2(q[uu], k[uu - ii + 6], acc[ii][uu]);
            }
        }
        __syncthreads();
    }

    if (active) {
        const float scale = 1.0f / 576.0f;   // 1 / (64 * 9)
#pragma unroll
        for (int ii = 0; ii < TI; ii++) {
            int i = ti * TI + ii;
            if (i >= D) continue;
            float* row = outbase + (size_t)i * ostride_i + 20 * tu;
#pragma unroll
            for (int uu = 0; uu < TU; uu++) {
                float2 v = *(float2*)&acc[ii][uu];
                v.x *= scale; v.y *= scale;
                *(float2*)(row + 2 * uu) = v;
            }
        }
    }
}

extern "C" void kernel_launch(void* const* d_in, const int* in_sizes, int n_in,
                              void* d_out, int out_size) {
    const float* in1 = (const float*)d_in[0];
    const float* in2 = (const float*)d_in[1];
    dim3 grid(D, H, BATCH);
    corr_kernel<<<grid, THREADS>>>(in1, in2, (float*)d_out);
}